// round 1
// baseline (speedup 1.0000x reference)
#include <cuda_runtime.h>
#include <cstdint>

// Scratch (static device globals — allocation-free per harness rules)
__device__ float g_P [8192 * 512];   // x @ W
__device__ float g_T1[2048 * 512];   // a0 * (s1 @ P)
__device__ float g_T3[6144 * 512];   // a1 * (s3 @ P)
__device__ float g_OL[8192 * 512];   // s0 @ T1

// ---------------------------------------------------------------------------
// 128x128 tile SGEMM, BK=8, 256 threads, 8x8 register blocking.
// MODE 0: C = A@B
// MODE 1: C = softmax(alpha)[aidx] * (A@B)
// MODE 2: C = relu(max(other, A@B) + bias)   (final epilogue)
// Requires M%128==0, N%128==0, K%8==0 (all shapes here satisfy this).
// ---------------------------------------------------------------------------
template <int MODE>
__global__ void __launch_bounds__(256, 2)
gemm128(const float* __restrict__ A, const float* __restrict__ B,
        float* __restrict__ C, int M, int N, int K,
        const float* __restrict__ alpha, int aidx,
        const float* __restrict__ other, const float* __restrict__ bias)
{
    __shared__ float As[8][128];
    __shared__ float Bs[8][128];

    const int tid  = threadIdx.x;
    const int brow = blockIdx.y * 128;
    const int bcol = blockIdx.x * 128;

    // Global-load assignments (one float4 from A, one from B per thread per k-step)
    const int arow  = tid >> 1;           // 0..127
    const int acol  = (tid & 1) * 4;      // 0 or 4
    const int bkrow = tid >> 5;           // 0..7
    const int bcol4 = (tid & 31) * 4;     // 0..124

    // Compute-tile assignment: 16x16 threads, each owns 8x8 outputs
    const int ty  = tid >> 4;
    const int tx  = tid & 15;
    const int row = ty * 8;
    const int col = tx * 8;

    const float* Aptr = A + (size_t)(brow + arow) * K + acol;
    const float* Bptr = B + (size_t)bkrow * N + bcol + bcol4;

    float acc[8][8];
#pragma unroll
    for (int i = 0; i < 8; i++)
#pragma unroll
        for (int j = 0; j < 8; j++) acc[i][j] = 0.0f;

    for (int k0 = 0; k0 < K; k0 += 8) {
        // Load A tile (transposed into SMEM) and B tile
        float4 av = *(const float4*)(Aptr + k0);
        float4 bv = *(const float4*)(Bptr + (size_t)k0 * N);
        As[acol + 0][arow] = av.x;
        As[acol + 1][arow] = av.y;
        As[acol + 2][arow] = av.z;
        As[acol + 3][arow] = av.w;
        *(float4*)&Bs[bkrow][bcol4] = bv;
        __syncthreads();

#pragma unroll
        for (int k = 0; k < 8; k++) {
            float4 a0 = *(const float4*)&As[k][row];
            float4 a1 = *(const float4*)&As[k][row + 4];
            float4 b0 = *(const float4*)&Bs[k][col];
            float4 b1 = *(const float4*)&Bs[k][col + 4];
            float a[8] = {a0.x, a0.y, a0.z, a0.w, a1.x, a1.y, a1.z, a1.w};
            float b[8] = {b0.x, b0.y, b0.z, b0.w, b1.x, b1.y, b1.z, b1.w};
#pragma unroll
            for (int i = 0; i < 8; i++)
#pragma unroll
                for (int j = 0; j < 8; j++)
                    acc[i][j] = fmaf(a[i], b[j], acc[i][j]);
        }
        __syncthreads();
    }

    // Epilogue
    float scale = 1.0f;
    if (MODE == 1) {
        float e0 = expf(alpha[0]);
        float e1 = expf(alpha[1]);
        scale = (aidx == 0 ? e0 : e1) / (e0 + e1);
    }

#pragma unroll
    for (int i = 0; i < 8; i++) {
        size_t cbase = (size_t)(brow + row + i) * N + bcol + col;
#pragma unroll
        for (int j4 = 0; j4 < 8; j4 += 4) {
            float4 v;
            v.x = acc[i][j4 + 0];
            v.y = acc[i][j4 + 1];
            v.z = acc[i][j4 + 2];
            v.w = acc[i][j4 + 3];
            if (MODE == 1) {
                v.x *= scale; v.y *= scale; v.z *= scale; v.w *= scale;
            }
            if (MODE == 2) {
                float4 o = *(const float4*)(other + cbase + j4);
                int bc = bcol + col + j4;
                v.x = fmaxf(fmaxf(v.x, o.x) + bias[bc + 0], 0.0f);
                v.y = fmaxf(fmaxf(v.y, o.y) + bias[bc + 1], 0.0f);
                v.z = fmaxf(fmaxf(v.z, o.z) + bias[bc + 2], 0.0f);
                v.w = fmaxf(fmaxf(v.w, o.w) + bias[bc + 3], 0.0f);
            }
            *(float4*)(C + cbase + j4) = v;
        }
    }
}

extern "C" void kernel_launch(void* const* d_in, const int* in_sizes, int n_in,
                              void* d_out, int out_size)
{
    const float* x     = (const float*)d_in[0];   // [8192, 512]
    const float* w     = (const float*)d_in[1];   // [512, 512]
    const float* alpha = (const float*)d_in[2];   // [2]
    const float* bias  = (const float*)d_in[3];   // [512]
    const float* s0    = (const float*)d_in[4];   // [8192, 2048]
    const float* s1    = (const float*)d_in[5];   // [2048, 8192]
    const float* s2    = (const float*)d_in[6];   // [8192, 6144]
    const float* s3    = (const float*)d_in[7];   // [6144, 8192]
    float* out = (float*)d_out;                   // [8192, 512]

    float *pP, *pT1, *pT3, *pOL;
    cudaGetSymbolAddress((void**)&pP,  g_P);
    cudaGetSymbolAddress((void**)&pT1, g_T1);
    cudaGetSymbolAddress((void**)&pT3, g_T3);
    cudaGetSymbolAddress((void**)&pOL, g_OL);

    dim3 blk(256);
    const int N = 8192, K = 2048, D = 512;

    // 1) P = x @ W                       [8192,512]
    gemm128<0><<<dim3(D / 128, N / 128), blk>>>(x, w, pP, N, D, D,
                                                nullptr, 0, nullptr, nullptr);
    // 2) T1 = a0 * (s1 @ P)              [2048,512]
    gemm128<1><<<dim3(D / 128, K / 128), blk>>>(s1, pP, pT1, K, D, N,
                                                alpha, 0, nullptr, nullptr);
    // 3) OL = s0 @ T1                    [8192,512]
    gemm128<0><<<dim3(D / 128, N / 128), blk>>>(s0, pT1, pOL, N, D, K,
                                                nullptr, 0, nullptr, nullptr);
    // 4) T3 = a1 * (s3 @ P)              [6144,512]
    gemm128<1><<<dim3(D / 128, (N - K) / 128), blk>>>(s3, pP, pT3, N - K, D, N,
                                                      alpha, 1, nullptr, nullptr);
    // 5) out = relu(max(OL, s2 @ T3) + bias)   [8192,512]
    gemm128<2><<<dim3(D / 128, N / 128), blk>>>(s2, pT3, out, N, D, N - K,
                                                alpha, 0, pOL, bias);
}

// round 3
// speedup vs baseline: 4.1909x; 4.1909x over previous
#include <cuda_runtime.h>
#include <cuda_bf16.h>
#include <cstdint>
#include <cstddef>

#define DINL __device__ __forceinline__

// ------------------------- problem sizes -------------------------
#define NN 8192
#define KK 2048
#define DD 512
#define NH (NN - KK)   // 6144

// ------------------------- scratch (static device globals) -------------------------
__device__ __nv_bfloat16 g_xh[NN*DD],  g_xl[NN*DD];
__device__ __nv_bfloat16 g_s0h[NN*KK], g_s0l[NN*KK];
__device__ __nv_bfloat16 g_s1h[KK*NN], g_s1l[KK*NN];
__device__ __nv_bfloat16 g_s2h[(size_t)NN*NH], g_s2l[(size_t)NN*NH];
__device__ __nv_bfloat16 g_s3h[(size_t)NH*NN], g_s3l[(size_t)NH*NN];
__device__ __nv_bfloat16 g_Wth[DD*DD],  g_Wtl[DD*DD];
__device__ __nv_bfloat16 g_Pth[DD*NN],  g_Ptl[DD*NN];
__device__ __nv_bfloat16 g_T1h[DD*KK],  g_T1l[DD*KK];
__device__ __nv_bfloat16 g_T3h[DD*NH],  g_T3l[DD*NH];
__device__ float g_P  [NN*DD];
__device__ float g_T1p[4*KK*DD];
__device__ float g_T3p[3*NH*DD];
__device__ float g_OL [NN*DD];

// ------------------------- ptx helpers (all base-ISA, no 'a' features) ----
DINL uint32_t smem_u32(const void* p) {
    uint32_t a;
    asm("{ .reg .u64 t; cvta.to.shared.u64 t, %1; cvt.u32.u64 %0, t; }" : "=r"(a) : "l"(p));
    return a;
}
DINL void cp16(uint32_t saddr, const void* g) {
    asm volatile("cp.async.cg.shared.global [%0], [%1], 16;" :: "r"(saddr), "l"(g));
}
DINL void cp_commit() { asm volatile("cp.async.commit_group;" ::: "memory"); }
DINL void cp_wait1()  { asm volatile("cp.async.wait_group 1;" ::: "memory"); }
DINL void cp_wait0()  { asm volatile("cp.async.wait_group 0;" ::: "memory"); }

DINL void ldsm4(uint32_t (&r)[4], uint32_t addr) {
    asm volatile("ldmatrix.sync.aligned.m8n8.x4.shared.b16 {%0,%1,%2,%3}, [%4];"
                 : "=r"(r[0]), "=r"(r[1]), "=r"(r[2]), "=r"(r[3]) : "r"(addr));
}
DINL void mma_bf16(float (&d)[4], const uint32_t (&a)[4], const uint32_t* b) {
    asm volatile(
        "mma.sync.aligned.m16n8k16.row.col.f32.bf16.bf16.f32 "
        "{%0,%1,%2,%3}, {%4,%5,%6,%7}, {%8,%9}, {%0,%1,%2,%3};"
        : "+f"(d[0]), "+f"(d[1]), "+f"(d[2]), "+f"(d[3])
        : "r"(a[0]), "r"(a[1]), "r"(a[2]), "r"(a[3]), "r"(b[0]), "r"(b[1]));
}

// ------------------------- GEMM -------------------------
// C[z][M,512] = A[M,K] @ Bt^T with bf16 hi/lo operand pairs (bf16x3 scheme).
// A: [M,K] bf16 row-major (h,l). Bt: [512,K] bf16 row-major (h,l).
// CTA tile 256x128, BK=64 (128B SW128 rows), 8 warps of 64x64, 2-stage cp.async.
static constexpr int OFF_AH = 0;
static constexpr int OFF_AL = 32768;
static constexpr int OFF_BH = 65536;
static constexpr int OFF_BL = 81920;
static constexpr int STAGE_BYTES = 98304;
static constexpr int GEMM_SMEM   = 2 * STAGE_BYTES;   // 192 KB

DINL void ld_sec(uint32_t sdst, const char* src, int row0, size_t pitch,
                 size_t kbyte, int nIter, int tid)
{
    for (int i = 0; i < nIter; i++) {
        int idx = tid * 16 + i * 4096;
        int row = idx >> 7, col = idx & 127;
        uint32_t sw = (uint32_t)idx ^ (((uint32_t)idx >> 3) & 0x70);
        cp16(sdst + sw, src + (size_t)(row0 + row) * pitch + kbyte + col);
    }
}

template <bool FINAL>
__global__ void __launch_bounds__(256, 1)
bfgemm(const __nv_bfloat16* __restrict__ Ah_, const __nv_bfloat16* __restrict__ Al_,
       const __nv_bfloat16* __restrict__ Bh_, const __nv_bfloat16* __restrict__ Bl_,
       float* __restrict__ C, int M, int K,
       const float* __restrict__ other, const float* __restrict__ bias)
{
    extern __shared__ char smem[];
    const uint32_t sb0 = smem_u32(smem);
    const int tid = threadIdx.x, wid = tid >> 5, lane = tid & 31;
    const int brow = blockIdx.y * 256, bcol = blockIdx.x * 128;
    const int warpM = (wid & 3) * 64, warpN = (wid >> 2) * 64;

    const int kchunks = K >> 6;
    const int Z = gridDim.z, z = blockIdx.z;
    const int kc0 = (int)(((long long)kchunks * z) / Z);
    const int kc1 = (int)(((long long)kchunks * (z + 1)) / Z);
    const int total = kc1 - kc0;
    float* Cz = C + (size_t)z * M * 512;

    const char* Ah = (const char*)Ah_;
    const char* Al = (const char*)Al_;
    const char* Bh = (const char*)Bh_;
    const char* Bl = (const char*)Bl_;
    const size_t pitch = (size_t)K * 2;

    // ldmatrix per-thread addressing (swizzle reduces to XOR by (lane&7)<<4)
    const uint32_t xorv = (uint32_t)(lane & 7) << 4;
    const uint32_t kaA = ((lane >> 4) & 1) * 16;   // A: lanes 16-31 take k+8 halves
    const uint32_t kbB = ((lane >> 3) & 1) * 16;   // B: lanes 8-15/24-31 take k+8
    uint32_t aRowOff[4], bRowOff[4];
#pragma unroll
    for (int am = 0; am < 4; am++)
        aRowOff[am] = (uint32_t)(warpM + am * 16 + (lane & 15)) * 128;
#pragma unroll
    for (int bg = 0; bg < 4; bg++)
        bRowOff[bg] = (uint32_t)(warpN + bg * 16 + ((lane >> 4) & 1) * 8 + (lane & 7)) * 128;

    float acc[4][8][4];
#pragma unroll
    for (int i = 0; i < 4; i++)
#pragma unroll
        for (int j = 0; j < 8; j++)
#pragma unroll
            for (int t = 0; t < 4; t++) acc[i][j][t] = 0.0f;

    // -------- pipeline prologue: fill both stages --------
#pragma unroll 1
    for (int p = 0; p < 2; p++) {
        uint32_t sb = sb0 + p * STAGE_BYTES;
        size_t kb = (size_t)(kc0 + p) * 128;
        ld_sec(sb + OFF_AH, Ah, brow, pitch, kb, 8, tid);
        ld_sec(sb + OFF_AL, Al, brow, pitch, kb, 8, tid);
        ld_sec(sb + OFF_BH, Bh, bcol, pitch, kb, 4, tid);
        ld_sec(sb + OFF_BL, Bl, bcol, pitch, kb, 4, tid);
        cp_commit();
    }

#pragma unroll 1
    for (int it = 0; it < total; ++it) {
        const int s = it & 1;
        if (it < total - 1) cp_wait1(); else cp_wait0();
        __syncthreads();

        const uint32_t sb = sb0 + s * STAGE_BYTES;
#pragma unroll 1
        for (int ks = 0; ks < 4; ks++) {
            const uint32_t kA = ((uint32_t)(ks * 32) + kaA) ^ xorv;
            const uint32_t kB = ((uint32_t)(ks * 32) + kbB) ^ xorv;
            uint32_t ah[4][4], al[4][4];
#pragma unroll
            for (int am = 0; am < 4; am++) {
                ldsm4(ah[am], sb + OFF_AH + aRowOff[am] + kA);
                ldsm4(al[am], sb + OFF_AL + aRowOff[am] + kA);
            }
#pragma unroll
            for (int bg = 0; bg < 4; bg++) {
                uint32_t bh[4], bl[4];
                ldsm4(bh, sb + OFF_BH + bRowOff[bg] + kB);
                ldsm4(bl, sb + OFF_BL + bRowOff[bg] + kB);
#pragma unroll
                for (int am = 0; am < 4; am++) {
#pragma unroll
                    for (int h = 0; h < 2; h++) {
                        float (&d)[4] = acc[am][bg * 2 + h];
                        mma_bf16(d, ah[am], bh + h * 2);
                        mma_bf16(d, ah[am], bl + h * 2);
                        mma_bf16(d, al[am], bh + h * 2);
                    }
                }
            }
        }
        __syncthreads();
        const int nx = it + 2;
        if (nx < total) {
            size_t kb = (size_t)(kc0 + nx) * 128;
            ld_sec(sb + OFF_AH, Ah, brow, pitch, kb, 8, tid);
            ld_sec(sb + OFF_AL, Al, brow, pitch, kb, 8, tid);
            ld_sec(sb + OFF_BH, Bh, bcol, pitch, kb, 4, tid);
            ld_sec(sb + OFF_BL, Bl, bcol, pitch, kb, 4, tid);
            cp_commit();
        }
    }

    // -------- epilogue --------
#pragma unroll
    for (int am = 0; am < 4; am++) {
#pragma unroll
        for (int bn = 0; bn < 8; bn++) {
            const int r0 = brow + warpM + am * 16 + (lane >> 2);
            const int cg = bcol + warpN + bn * 8 + (lane & 3) * 2;
#pragma unroll
            for (int h = 0; h < 2; h++) {
                const int row = r0 + h * 8;
                float2 v = make_float2(acc[am][bn][h * 2], acc[am][bn][h * 2 + 1]);
                size_t o = (size_t)row * 512 + cg;
                if (FINAL) {
                    float2 ov = *(const float2*)(other + o);
                    float2 bb = *(const float2*)(bias + cg);
                    v.x = fmaxf(fmaxf(v.x, ov.x) + bb.x, 0.0f);
                    v.y = fmaxf(fmaxf(v.y, ov.y) + bb.y, 0.0f);
                }
                *(float2*)(Cz + o) = v;
            }
        }
    }
}

// ------------------------- split fp32 -> bf16 hi/lo -------------------------
__global__ void splitk(const float* __restrict__ src, __nv_bfloat16* __restrict__ h,
                       __nv_bfloat16* __restrict__ l, size_t n4)
{
    size_t stride = (size_t)gridDim.x * blockDim.x;
    for (size_t i = (size_t)blockIdx.x * blockDim.x + threadIdx.x; i < n4; i += stride) {
        float4 v = ((const float4*)src)[i];
        __nv_bfloat16 h0 = __float2bfloat16(v.x), h1 = __float2bfloat16(v.y);
        __nv_bfloat16 h2 = __float2bfloat16(v.z), h3 = __float2bfloat16(v.w);
        __nv_bfloat16 l0 = __float2bfloat16(v.x - __bfloat162float(h0));
        __nv_bfloat16 l1 = __float2bfloat16(v.y - __bfloat162float(h1));
        __nv_bfloat16 l2 = __float2bfloat16(v.z - __bfloat162float(h2));
        __nv_bfloat16 l3 = __float2bfloat16(v.w - __bfloat162float(h3));
        uint2 hp, lp;
        hp.x = (uint32_t)__bfloat16_as_ushort(h0) | ((uint32_t)__bfloat16_as_ushort(h1) << 16);
        hp.y = (uint32_t)__bfloat16_as_ushort(h2) | ((uint32_t)__bfloat16_as_ushort(h3) << 16);
        lp.x = (uint32_t)__bfloat16_as_ushort(l0) | ((uint32_t)__bfloat16_as_ushort(l1) << 16);
        lp.y = (uint32_t)__bfloat16_as_ushort(l2) | ((uint32_t)__bfloat16_as_ushort(l3) << 16);
        ((uint2*)h)[i] = hp;
        ((uint2*)l)[i] = lp;
    }
}

// ------------------- combine(split-K) + scale + transpose + split ----------
// in: parts [Z, Min, 512] fp32. out: th/tl [512, Min] bf16 scaled by softmax(alpha)[aidx].
__global__ void cst(const float* __restrict__ parts, int Z, int Min,
                    __nv_bfloat16* __restrict__ th, __nv_bfloat16* __restrict__ tl,
                    const float* __restrict__ alpha, int aidx)
{
    __shared__ float tile[32][33];
    const int m0 = blockIdx.x * 32, n0 = blockIdx.y * 32;
    const int tx = threadIdx.x, ty = threadIdx.y;   // 32 x 8
    float s = 1.0f;
    if (aidx >= 0) {
        float e0 = __expf(alpha[0]), e1 = __expf(alpha[1]);
        s = (aidx == 0 ? e0 : e1) / (e0 + e1);
    }
#pragma unroll
    for (int j = 0; j < 32; j += 8) {
        int m = m0 + ty + j;
        float acc = 0.0f;
        for (int zz = 0; zz < Z; zz++)
            acc += parts[((size_t)zz * Min + m) * 512 + n0 + tx];
        tile[ty + j][tx] = acc * s;
    }
    __syncthreads();
#pragma unroll
    for (int j = 0; j < 32; j += 8) {
        float v = tile[tx][ty + j];
        __nv_bfloat16 h = __float2bfloat16(v);
        __nv_bfloat16 l = __float2bfloat16(v - __bfloat162float(h));
        size_t o = (size_t)(n0 + ty + j) * Min + m0 + tx;
        th[o] = h;
        tl[o] = l;
    }
}

// ------------------------- host -------------------------
extern "C" void kernel_launch(void* const* d_in, const int* in_sizes, int n_in,
                              void* d_out, int out_size)
{
    const float* x     = (const float*)d_in[0];
    const float* w     = (const float*)d_in[1];
    const float* alpha = (const float*)d_in[2];
    const float* bias  = (const float*)d_in[3];
    const float* s0    = (const float*)d_in[4];
    const float* s1    = (const float*)d_in[5];
    const float* s2    = (const float*)d_in[6];
    const float* s3    = (const float*)d_in[7];
    float* out = (float*)d_out;

    __nv_bfloat16 *xh, *xl, *s0h, *s0l, *s1h, *s1l, *s2h, *s2l, *s3h, *s3l;
    __nv_bfloat16 *Wth, *Wtl, *Pth, *Ptl, *T1h, *T1l, *T3h, *T3l;
    float *pP, *pT1p, *pT3p, *pOL;
    cudaGetSymbolAddress((void**)&xh,  g_xh);  cudaGetSymbolAddress((void**)&xl,  g_xl);
    cudaGetSymbolAddress((void**)&s0h, g_s0h); cudaGetSymbolAddress((void**)&s0l, g_s0l);
    cudaGetSymbolAddress((void**)&s1h, g_s1h); cudaGetSymbolAddress((void**)&s1l, g_s1l);
    cudaGetSymbolAddress((void**)&s2h, g_s2h); cudaGetSymbolAddress((void**)&s2l, g_s2l);
    cudaGetSymbolAddress((void**)&s3h, g_s3h); cudaGetSymbolAddress((void**)&s3l, g_s3l);
    cudaGetSymbolAddress((void**)&Wth, g_Wth); cudaGetSymbolAddress((void**)&Wtl, g_Wtl);
    cudaGetSymbolAddress((void**)&Pth, g_Pth); cudaGetSymbolAddress((void**)&Ptl, g_Ptl);
    cudaGetSymbolAddress((void**)&T1h, g_T1h); cudaGetSymbolAddress((void**)&T1l, g_T1l);
    cudaGetSymbolAddress((void**)&T3h, g_T3h); cudaGetSymbolAddress((void**)&T3l, g_T3l);
    cudaGetSymbolAddress((void**)&pP,  g_P);   cudaGetSymbolAddress((void**)&pT1p, g_T1p);
    cudaGetSymbolAddress((void**)&pT3p, g_T3p); cudaGetSymbolAddress((void**)&pOL, g_OL);

    cudaFuncSetAttribute(bfgemm<false>, cudaFuncAttributeMaxDynamicSharedMemorySize, GEMM_SMEM);
    cudaFuncSetAttribute(bfgemm<true>,  cudaFuncAttributeMaxDynamicSharedMemorySize, GEMM_SMEM);

    // operand splits
    splitk<<<1024, 256>>>(x,  xh,  xl,  (size_t)NN * DD / 4);
    splitk<<<1024, 256>>>(s0, s0h, s0l, (size_t)NN * KK / 4);
    splitk<<<1024, 256>>>(s1, s1h, s1l, (size_t)KK * NN / 4);
    splitk<<<2048, 256>>>(s2, s2h, s2l, (size_t)NN * NH / 4);
    splitk<<<2048, 256>>>(s3, s3h, s3l, (size_t)NH * NN / 4);
    // W -> Wt (transpose + split)
    cst<<<dim3(DD / 32, 16), dim3(32, 8)>>>(w, 1, DD, Wth, Wtl, alpha, -1);

    // G1: P = x @ W        [8192,512], K=512
    bfgemm<false><<<dim3(4, 32, 1), 256, GEMM_SMEM>>>(xh, xl, Wth, Wtl, pP, NN, DD, nullptr, nullptr);
    // P -> Pt
    cst<<<dim3(NN / 32, 16), dim3(32, 8)>>>(pP, 1, NN, Pth, Ptl, alpha, -1);
    // G2: T1 = s1 @ P      [2048,512], K=8192, split-K=4
    bfgemm<false><<<dim3(4, 8, 4), 256, GEMM_SMEM>>>(s1h, s1l, Pth, Ptl, pT1p, KK, NN, nullptr, nullptr);
    cst<<<dim3(KK / 32, 16), dim3(32, 8)>>>(pT1p, 4, KK, T1h, T1l, alpha, 0);
    // G3: OL = s0 @ T1     [8192,512], K=2048
    bfgemm<false><<<dim3(4, 32, 1), 256, GEMM_SMEM>>>(s0h, s0l, T1h, T1l, pOL, NN, KK, nullptr, nullptr);
    // G4: T3 = s3 @ P      [6144,512], K=8192, split-K=3
    bfgemm<false><<<dim3(4, 24, 3), 256, GEMM_SMEM>>>(s3h, s3l, Pth, Ptl, pT3p, NH, NN, nullptr, nullptr);
    cst<<<dim3(NH / 32, 16), dim3(32, 8)>>>(pT3p, 3, NH, T3h, T3l, alpha, 1);
    // G5: out = relu(max(OL, s2 @ T3) + bias)   [8192,512], K=6144
    bfgemm<true><<<dim3(4, 32, 1), 256, GEMM_SMEM>>>(s2h, s2l, T3h, T3l, out, NN, NH, pOL, bias);
}

// round 4
// speedup vs baseline: 4.1925x; 1.0004x over previous
#include <cuda_runtime.h>
#include <cuda_bf16.h>
#include <cstdint>
#include <cstddef>

#define DINL __device__ __forceinline__

// ------------------------- problem sizes -------------------------
#define NN 8192
#define KK 2048
#define DD 512
#define NH (NN - KK)   // 6144

// ------------------------- scratch (static device globals) -------------------------
__device__ __nv_bfloat16 g_xh[NN*DD],  g_xl[NN*DD];
__device__ __nv_bfloat16 g_s0h[NN*KK], g_s0l[NN*KK];
__device__ __nv_bfloat16 g_s1h[KK*NN], g_s1l[KK*NN];
__device__ __nv_bfloat16 g_s2h[(size_t)NN*NH], g_s2l[(size_t)NN*NH];
__device__ __nv_bfloat16 g_s3h[(size_t)NH*NN], g_s3l[(size_t)NH*NN];
__device__ __nv_bfloat16 g_Wth[DD*DD],  g_Wtl[DD*DD];
__device__ __nv_bfloat16 g_Pth[DD*NN],  g_Ptl[DD*NN];
__device__ __nv_bfloat16 g_T1h[DD*KK],  g_T1l[DD*KK];
__device__ __nv_bfloat16 g_T3h[DD*NH],  g_T3l[DD*NH];
__device__ float g_P  [NN*DD];
__device__ float g_T1p[4*KK*DD];
__device__ float g_T3p[3*NH*DD];
__device__ float g_OL [NN*DD];

// ------------------------- ptx helpers (base ISA only) ----
DINL uint32_t smem_u32(const void* p) {
    uint32_t a;
    asm("{ .reg .u64 t; cvta.to.shared.u64 t, %1; cvt.u32.u64 %0, t; }" : "=r"(a) : "l"(p));
    return a;
}
DINL void cp16(uint32_t saddr, const void* g) {
    asm volatile("cp.async.cg.shared.global [%0], [%1], 16;" :: "r"(saddr), "l"(g));
}
DINL void cp_commit() { asm volatile("cp.async.commit_group;" ::: "memory"); }
DINL void cp_wait1()  { asm volatile("cp.async.wait_group 1;" ::: "memory"); }
DINL void cp_wait0()  { asm volatile("cp.async.wait_group 0;" ::: "memory"); }

DINL void ldsm4(uint32_t (&r)[4], uint32_t addr) {
    asm volatile("ldmatrix.sync.aligned.m8n8.x4.shared.b16 {%0,%1,%2,%3}, [%4];"
                 : "=r"(r[0]), "=r"(r[1]), "=r"(r[2]), "=r"(r[3]) : "r"(addr));
}
DINL void mma_bf16(float (&d)[4], const uint32_t (&a)[4], const uint32_t* b) {
    asm volatile(
        "mma.sync.aligned.m16n8k16.row.col.f32.bf16.bf16.f32 "
        "{%0,%1,%2,%3}, {%4,%5,%6,%7}, {%8,%9}, {%0,%1,%2,%3};"
        : "+f"(d[0]), "+f"(d[1]), "+f"(d[2]), "+f"(d[3])
        : "r"(a[0]), "r"(a[1]), "r"(a[2]), "r"(a[3]), "r"(b[0]), "r"(b[1]));
}

// ------------------------- GEMM -------------------------
// C[z][M,512] = A[M,K] @ Bt^T with bf16 hi/lo pairs (bf16x3 scheme).
// CTA tile 256x128, BK=64 (128B SW128 rows), 8 warps of 64x64, 2-stage cp.async.
static constexpr int OFF_AH = 0;
static constexpr int OFF_AL = 32768;
static constexpr int OFF_BH = 65536;
static constexpr int OFF_BL = 81920;
static constexpr int STAGE_BYTES = 98304;
static constexpr int GEMM_SMEM   = 2 * STAGE_BYTES;   // 192 KB

DINL void ld_sec(uint32_t sdst, const char* src, int row0, size_t pitch,
                 size_t kbyte, int nIter, int tid)
{
    for (int i = 0; i < nIter; i++) {
        int idx = tid * 16 + i * 4096;
        int row = idx >> 7, col = idx & 127;
        uint32_t sw = (uint32_t)idx ^ (((uint32_t)idx >> 3) & 0x70);
        cp16(sdst + sw, src + (size_t)(row0 + row) * pitch + kbyte + col);
    }
}

template <bool FINAL>
__global__ void __launch_bounds__(256, 1)
bfgemm(const __nv_bfloat16* __restrict__ Ah_, const __nv_bfloat16* __restrict__ Al_,
       const __nv_bfloat16* __restrict__ Bh_, const __nv_bfloat16* __restrict__ Bl_,
       float* __restrict__ C, int M, int K,
       const float* __restrict__ other, const float* __restrict__ bias)
{
    extern __shared__ char smem[];
    const uint32_t sb0 = smem_u32(smem);
    const int tid = threadIdx.x, wid = tid >> 5, lane = tid & 31;
    const int brow = blockIdx.y * 256, bcol = blockIdx.x * 128;
    const int warpM = (wid & 3) * 64, warpN = (wid >> 2) * 64;

    const int kchunks = K >> 6;
    const int Z = gridDim.z, z = blockIdx.z;
    const int kc0 = (int)(((long long)kchunks * z) / Z);
    const int kc1 = (int)(((long long)kchunks * (z + 1)) / Z);
    const int total = kc1 - kc0;
    float* Cz = C + (size_t)z * M * 512;

    const char* Ah = (const char*)Ah_;
    const char* Al = (const char*)Al_;
    const char* Bh = (const char*)Bh_;
    const char* Bl = (const char*)Bl_;
    const size_t pitch = (size_t)K * 2;

    const uint32_t xorv = (uint32_t)(lane & 7) << 4;
    const uint32_t kaA = ((lane >> 4) & 1) * 16;
    const uint32_t kbB = ((lane >> 3) & 1) * 16;
    uint32_t aRowOff[4], bRowOff[4];
#pragma unroll
    for (int am = 0; am < 4; am++)
        aRowOff[am] = (uint32_t)(warpM + am * 16 + (lane & 15)) * 128;
#pragma unroll
    for (int bg = 0; bg < 4; bg++)
        bRowOff[bg] = (uint32_t)(warpN + bg * 16 + ((lane >> 4) & 1) * 8 + (lane & 7)) * 128;

    float acc[4][8][4];
#pragma unroll
    for (int i = 0; i < 4; i++)
#pragma unroll
        for (int j = 0; j < 8; j++)
#pragma unroll
            for (int t = 0; t < 4; t++) acc[i][j][t] = 0.0f;

    // pipeline prologue: fill both stages
#pragma unroll 1
    for (int p = 0; p < 2; p++) {
        uint32_t sb = sb0 + p * STAGE_BYTES;
        size_t kb = (size_t)(kc0 + p) * 128;
        ld_sec(sb + OFF_AH, Ah, brow, pitch, kb, 8, tid);
        ld_sec(sb + OFF_AL, Al, brow, pitch, kb, 8, tid);
        ld_sec(sb + OFF_BH, Bh, bcol, pitch, kb, 4, tid);
        ld_sec(sb + OFF_BL, Bl, bcol, pitch, kb, 4, tid);
        cp_commit();
    }

#pragma unroll 1
    for (int it = 0; it < total; ++it) {
        const int s = it & 1;
        if (it < total - 1) cp_wait1(); else cp_wait0();
        __syncthreads();

        const uint32_t sb = sb0 + s * STAGE_BYTES;
#pragma unroll 1
        for (int ks = 0; ks < 4; ks++) {
            const uint32_t kA = ((uint32_t)(ks * 32) + kaA) ^ xorv;
            const uint32_t kB = ((uint32_t)(ks * 32) + kbB) ^ xorv;
            uint32_t ah[4][4], al[4][4];
#pragma unroll
            for (int am = 0; am < 4; am++) {
                ldsm4(ah[am], sb + OFF_AH + aRowOff[am] + kA);
                ldsm4(al[am], sb + OFF_AL + aRowOff[am] + kA);
            }
#pragma unroll
            for (int bg = 0; bg < 4; bg++) {
                uint32_t bh[4], bl[4];
                ldsm4(bh, sb + OFF_BH + bRowOff[bg] + kB);
                ldsm4(bl, sb + OFF_BL + bRowOff[bg] + kB);
                // pass-separated ordering: 8 independent accumulators between
                // successive MMAs on the same accumulator -> no RAW stalls
#pragma unroll
                for (int am = 0; am < 4; am++)
#pragma unroll
                    for (int h = 0; h < 2; h++)
                        mma_bf16(acc[am][bg * 2 + h], ah[am], bh + h * 2);
#pragma unroll
                for (int am = 0; am < 4; am++)
#pragma unroll
                    for (int h = 0; h < 2; h++)
                        mma_bf16(acc[am][bg * 2 + h], ah[am], bl + h * 2);
#pragma unroll
                for (int am = 0; am < 4; am++)
#pragma unroll
                    for (int h = 0; h < 2; h++)
                        mma_bf16(acc[am][bg * 2 + h], al[am], bh + h * 2);
            }
        }
        __syncthreads();
        const int nx = it + 2;
        if (nx < total) {
            size_t kb = (size_t)(kc0 + nx) * 128;
            ld_sec(sb + OFF_AH, Ah, brow, pitch, kb, 8, tid);
            ld_sec(sb + OFF_AL, Al, brow, pitch, kb, 8, tid);
            ld_sec(sb + OFF_BH, Bh, bcol, pitch, kb, 4, tid);
            ld_sec(sb + OFF_BL, Bl, bcol, pitch, kb, 4, tid);
            cp_commit();
        }
    }

    // epilogue
#pragma unroll
    for (int am = 0; am < 4; am++) {
#pragma unroll
        for (int bn = 0; bn < 8; bn++) {
            const int r0 = brow + warpM + am * 16 + (lane >> 2);
            const int cg = bcol + warpN + bn * 8 + (lane & 3) * 2;
#pragma unroll
            for (int h = 0; h < 2; h++) {
                const int row = r0 + h * 8;
                float2 v = make_float2(acc[am][bn][h * 2], acc[am][bn][h * 2 + 1]);
                size_t o = (size_t)row * 512 + cg;
                if (FINAL) {
                    float2 ov = *(const float2*)(other + o);
                    float2 bb = *(const float2*)(bias + cg);
                    v.x = fmaxf(fmaxf(v.x, ov.x) + bb.x, 0.0f);
                    v.y = fmaxf(fmaxf(v.y, ov.y) + bb.y, 0.0f);
                }
                *(float2*)(Cz + o) = v;
            }
        }
    }
}

// ------------------------- split fp32 -> bf16 hi/lo -------------------------
__global__ void splitk(const float* __restrict__ src, __nv_bfloat16* __restrict__ h,
                       __nv_bfloat16* __restrict__ l, size_t n4)
{
    size_t stride = (size_t)gridDim.x * blockDim.x;
    for (size_t i = (size_t)blockIdx.x * blockDim.x + threadIdx.x; i < n4; i += stride) {
        float4 v = ((const float4*)src)[i];
        __nv_bfloat16 h0 = __float2bfloat16(v.x), h1 = __float2bfloat16(v.y);
        __nv_bfloat16 h2 = __float2bfloat16(v.z), h3 = __float2bfloat16(v.w);
        __nv_bfloat16 l0 = __float2bfloat16(v.x - __bfloat162float(h0));
        __nv_bfloat16 l1 = __float2bfloat16(v.y - __bfloat162float(h1));
        __nv_bfloat16 l2 = __float2bfloat16(v.z - __bfloat162float(h2));
        __nv_bfloat16 l3 = __float2bfloat16(v.w - __bfloat162float(h3));
        uint2 hp, lp;
        hp.x = (uint32_t)__bfloat16_as_ushort(h0) | ((uint32_t)__bfloat16_as_ushort(h1) << 16);
        hp.y = (uint32_t)__bfloat16_as_ushort(h2) | ((uint32_t)__bfloat16_as_ushort(h3) << 16);
        lp.x = (uint32_t)__bfloat16_as_ushort(l0) | ((uint32_t)__bfloat16_as_ushort(l1) << 16);
        lp.y = (uint32_t)__bfloat16_as_ushort(l2) | ((uint32_t)__bfloat16_as_ushort(l3) << 16);
        ((uint2*)h)[i] = hp;
        ((uint2*)l)[i] = lp;
    }
}

// ------------------- combine(split-K) + scale + transpose + split ----------
__global__ void cst(const float* __restrict__ parts, int Z, int Min,
                    __nv_bfloat16* __restrict__ th, __nv_bfloat16* __restrict__ tl,
                    const float* __restrict__ alpha, int aidx)
{
    __shared__ float tile[32][33];
    const int m0 = blockIdx.x * 32, n0 = blockIdx.y * 32;
    const int tx = threadIdx.x, ty = threadIdx.y;   // 32 x 8
    float s = 1.0f;
    if (aidx >= 0) {
        float e0 = __expf(alpha[0]), e1 = __expf(alpha[1]);
        s = (aidx == 0 ? e0 : e1) / (e0 + e1);
    }
#pragma unroll
    for (int j = 0; j < 32; j += 8) {
        int m = m0 + ty + j;
        float acc = 0.0f;
        for (int zz = 0; zz < Z; zz++)
            acc += parts[((size_t)zz * Min + m) * 512 + n0 + tx];
        tile[ty + j][tx] = acc * s;
    }
    __syncthreads();
#pragma unroll
    for (int j = 0; j < 32; j += 8) {
        float v = tile[tx][ty + j];
        __nv_bfloat16 h = __float2bfloat16(v);
        __nv_bfloat16 l = __float2bfloat16(v - __bfloat162float(h));
        size_t o = (size_t)(n0 + ty + j) * Min + m0 + tx;
        th[o] = h;
        tl[o] = l;
    }
}

// ------------------------- host -------------------------
extern "C" void kernel_launch(void* const* d_in, const int* in_sizes, int n_in,
                              void* d_out, int out_size)
{
    const float* x     = (const float*)d_in[0];
    const float* w     = (const float*)d_in[1];
    const float* alpha = (const float*)d_in[2];
    const float* bias  = (const float*)d_in[3];
    const float* s0    = (const float*)d_in[4];
    const float* s1    = (const float*)d_in[5];
    const float* s2    = (const float*)d_in[6];
    const float* s3    = (const float*)d_in[7];
    float* out = (float*)d_out;

    __nv_bfloat16 *xh, *xl, *s0h, *s0l, *s1h, *s1l, *s2h, *s2l, *s3h, *s3l;
    __nv_bfloat16 *Wth, *Wtl, *Pth, *Ptl, *T1h, *T1l, *T3h, *T3l;
    float *pP, *pT1p, *pT3p, *pOL;
    cudaGetSymbolAddress((void**)&xh,  g_xh);  cudaGetSymbolAddress((void**)&xl,  g_xl);
    cudaGetSymbolAddress((void**)&s0h, g_s0h); cudaGetSymbolAddress((void**)&s0l, g_s0l);
    cudaGetSymbolAddress((void**)&s1h, g_s1h); cudaGetSymbolAddress((void**)&s1l, g_s1l);
    cudaGetSymbolAddress((void**)&s2h, g_s2h); cudaGetSymbolAddress((void**)&s2l, g_s2l);
    cudaGetSymbolAddress((void**)&s3h, g_s3h); cudaGetSymbolAddress((void**)&s3l, g_s3l);
    cudaGetSymbolAddress((void**)&Wth, g_Wth); cudaGetSymbolAddress((void**)&Wtl, g_Wtl);
    cudaGetSymbolAddress((void**)&Pth, g_Pth); cudaGetSymbolAddress((void**)&Ptl, g_Ptl);
    cudaGetSymbolAddress((void**)&T1h, g_T1h); cudaGetSymbolAddress((void**)&T1l, g_T1l);
    cudaGetSymbolAddress((void**)&T3h, g_T3h); cudaGetSymbolAddress((void**)&T3l, g_T3l);
    cudaGetSymbolAddress((void**)&pP,  g_P);   cudaGetSymbolAddress((void**)&pT1p, g_T1p);
    cudaGetSymbolAddress((void**)&pT3p, g_T3p); cudaGetSymbolAddress((void**)&pOL, g_OL);

    cudaFuncSetAttribute(bfgemm<false>, cudaFuncAttributeMaxDynamicSharedMemorySize, GEMM_SMEM);
    cudaFuncSetAttribute(bfgemm<true>,  cudaFuncAttributeMaxDynamicSharedMemorySize, GEMM_SMEM);

    // Launch order arranged so the 6th launch (ncu -s 5 -c 1 capture) is G4,
    // the largest GEMM. All dependencies preserved.
    splitk<<<1024, 256>>>(x,  xh,  xl,  (size_t)NN * DD / 4);                            // 1
    splitk<<<2048, 256>>>(s3, s3h, s3l, (size_t)NH * NN / 4);                            // 2
    cst<<<dim3(DD / 32, 16), dim3(32, 8)>>>(w, 1, DD, Wth, Wtl, alpha, -1);              // 3
    // G1: P = x @ W        [8192,512], K=512
    bfgemm<false><<<dim3(4, 32, 1), 256, GEMM_SMEM>>>(xh, xl, Wth, Wtl, pP, NN, DD,      // 4
                                                      nullptr, nullptr);
    cst<<<dim3(NN / 32, 16), dim3(32, 8)>>>(pP, 1, NN, Pth, Ptl, alpha, -1);             // 5
    // G4: T3 = s3 @ P      [6144,512], K=8192, split-K=3   <- profiled launch
    bfgemm<false><<<dim3(4, 24, 3), 256, GEMM_SMEM>>>(s3h, s3l, Pth, Ptl, pT3p, NH, NN,  // 6
                                                      nullptr, nullptr);
    splitk<<<1024, 256>>>(s1, s1h, s1l, (size_t)KK * NN / 4);                            // 7
    // G2: T1 = s1 @ P      [2048,512], K=8192, split-K=4
    bfgemm<false><<<dim3(4, 8, 4), 256, GEMM_SMEM>>>(s1h, s1l, Pth, Ptl, pT1p, KK, NN,   // 8
                                                     nullptr, nullptr);
    cst<<<dim3(KK / 32, 16), dim3(32, 8)>>>(pT1p, 4, KK, T1h, T1l, alpha, 0);            // 9
    splitk<<<1024, 256>>>(s0, s0h, s0l, (size_t)NN * KK / 4);                            // 10
    // G3: OL = s0 @ T1     [8192,512], K=2048
    bfgemm<false><<<dim3(4, 32, 1), 256, GEMM_SMEM>>>(s0h, s0l, T1h, T1l, pOL, NN, KK,   // 11
                                                      nullptr, nullptr);
    cst<<<dim3(NH / 32, 16), dim3(32, 8)>>>(pT3p, 3, NH, T3h, T3l, alpha, 1);            // 12
    splitk<<<2048, 256>>>(s2, s2h, s2l, (size_t)NN * NH / 4);                            // 13
    // G5: out = relu(max(OL, s2 @ T3) + bias)   [8192,512], K=6144
    bfgemm<true><<<dim3(4, 32, 1), 256, GEMM_SMEM>>>(s2h, s2l, T3h, T3l, out, NN, NH,    // 14
                                                     pOL, bias);
}